// round 1
// baseline (speedup 1.0000x reference)
#include <cuda_runtime.h>
#include <cstdint>

// ---------------------------------------------------------------------------
// FasterRCNN RPN proposal filtering:
//   per image (N=8): top-2000 of 1M logits -> decode/clip boxes -> valid mask
//   -> greedy NMS (IoU>0.7) -> stable top-1000 (kept first, then padding)
// Output: [N, 1000, 5] = x1,y1,x2,y2,score
// ---------------------------------------------------------------------------

#define NMAXI 8
#define PRE   2000
#define POST  1000
#define CAP   2048
#define WORDS 32
#define TIECAP 1024

#define IMGSZ 800.0f
#define IOUTHR 0.7f
#define MINSZ 1e-3f
#define BBOXCLIP 4.135166556742356f   // log(1000/16)

// ------------------------- device scratch (static) -------------------------
__device__ unsigned int       d_hist[NMAXI][256];
__device__ unsigned int       d_prefix[NMAXI];
__device__ int                d_rankr[NMAXI];
__device__ int                d_cntG[NMAXI];
__device__ int                d_cntE[NMAXI];
__device__ int                d_tie[NMAXI][TIECAP];
__device__ unsigned long long d_cand[NMAXI][CAP];
__device__ float              d_bx1[NMAXI][CAP], d_by1[NMAXI][CAP];
__device__ float              d_bx2[NMAXI][CAP], d_by2[NMAXI][CAP];
__device__ float              d_area[NMAXI][CAP], d_scoreA[NMAXI][CAP];
__device__ unsigned char      d_validb[NMAXI][CAP];
__device__ unsigned long long d_mask[NMAXI][CAP][WORDS];   // 4 MB
__device__ unsigned long long d_keep[NMAXI][WORDS];

// monotone float->uint transform (desc on key == desc on float)
__device__ __forceinline__ unsigned key_of(float f) {
    unsigned u = __float_as_uint(f);
    return (u & 0x80000000u) ? ~u : (u | 0x80000000u);
}

// ------------------------------- kernels -----------------------------------
__global__ void k_init() {
    int img = blockIdx.x;
    d_hist[img][threadIdx.x] = 0u;
    if (threadIdx.x == 0) {
        d_prefix[img] = 0u;
        d_rankr[img]  = PRE;
        d_cntG[img]   = 0;
        d_cntE[img]   = 0;
    }
}

__global__ void k_hist(const float* __restrict__ obj, int A, int pass) {
    __shared__ unsigned int sh[256];
    int img = blockIdx.y;
    sh[threadIdx.x] = 0u;
    __syncthreads();
    unsigned pref = d_prefix[img];
    int shift = 24 - 8 * pass;
    int stride = gridDim.x * blockDim.x;
    for (int i = blockIdx.x * blockDim.x + threadIdx.x; i < A; i += stride) {
        unsigned u = key_of(obj[(size_t)img * A + i]);
        bool m = (pass == 0) || (((u ^ pref) >> (shift + 8)) == 0u);
        if (m) atomicAdd(&sh[(u >> shift) & 255u], 1u);
    }
    __syncthreads();
    if (sh[threadIdx.x]) atomicAdd(&d_hist[img][threadIdx.x], sh[threadIdx.x]);
}

__global__ void k_pick(int pass) {
    int img = threadIdx.x;
    int shift = 24 - 8 * pass;
    unsigned R = (unsigned)d_rankr[img];
    unsigned acc = 0;
    int b = 0;
    for (int v = 255; v >= 0; v--) {
        unsigned h = d_hist[img][v];
        if (acc + h >= R) { b = v; break; }
        acc += h;
    }
    d_rankr[img]  = (int)(R - acc);
    d_prefix[img] |= ((unsigned)b) << shift;
    for (int v = 0; v < 256; v++) d_hist[img][v] = 0u;  // reset for next pass
}

__global__ void k_compact(const float* __restrict__ obj, int A) {
    int img = blockIdx.y;
    unsigned T = d_prefix[img];
    int stride = gridDim.x * blockDim.x;
    for (int i = blockIdx.x * blockDim.x + threadIdx.x; i < A; i += stride) {
        unsigned u = key_of(obj[(size_t)img * A + i]);
        if (u > T) {
            int pos = atomicAdd(&d_cntG[img], 1);
            if (pos < CAP)
                d_cand[img][pos] = ((unsigned long long)u << 32) | (unsigned)(~(unsigned)i);
        } else if (u == T) {
            int pos = atomicAdd(&d_cntE[img], 1);
            if (pos < TIECAP) d_tie[img][pos] = i;
        }
    }
}

// fill ties, pad, bitonic sort 2048 descending (key desc, ties: index asc)
__global__ void k_sortfill() {
    __shared__ unsigned long long sh[CAP];
    int img = blockIdx.x;
    int cg = d_cntG[img]; if (cg > PRE) cg = PRE;
    for (int idx = threadIdx.x; idx < CAP; idx += blockDim.x)
        sh[idx] = (idx < cg) ? d_cand[img][idx] : 0ull;
    __syncthreads();
    if (threadIdx.x == 0) {
        int ce = d_cntE[img]; if (ce > TIECAP) ce = TIECAP;
        int need = PRE - cg; if (need < 0) need = 0; if (need > ce) need = ce;
        unsigned long long T64 = (unsigned long long)d_prefix[img] << 32;
        for (int r = 0; r < need; r++) {          // take `need` smallest tie indices
            int best = -1, bi = 0;
            for (int t = 0; t < ce; t++) {
                int v = d_tie[img][t];
                if (v >= 0 && (best < 0 || v < best)) { best = v; bi = t; }
            }
            d_tie[img][bi] = -1;
            sh[cg + r] = T64 | (unsigned)(~(unsigned)best);
        }
    }
    __syncthreads();
    // bitonic sort descending
    for (unsigned k = 2; k <= CAP; k <<= 1) {
        for (unsigned j = k >> 1; j > 0; j >>= 1) {
            for (unsigned idx = threadIdx.x; idx < CAP; idx += blockDim.x) {
                unsigned ixj = idx ^ j;
                if (ixj > idx) {
                    bool up = ((idx & k) == 0);
                    unsigned long long a = sh[idx], b = sh[ixj];
                    bool sw = up ? (a < b) : (a > b);
                    if (sw) { sh[idx] = b; sh[ixj] = a; }
                }
            }
            __syncthreads();
        }
    }
    for (int idx = threadIdx.x; idx < CAP; idx += blockDim.x)
        d_cand[img][idx] = sh[idx];
}

__global__ void k_decode(const float* __restrict__ deltas,
                         const float* __restrict__ anchors, int A, int N) {
    int t = blockIdx.x * blockDim.x + threadIdx.x;
    if (t >= N * PRE) return;
    int img = t / PRE, s = t % PRE;
    unsigned long long pk = d_cand[img][s];
    unsigned idx = ~(unsigned)(pk & 0xffffffffu);
    unsigned kk  = (unsigned)(pk >> 32);
    unsigned ub  = (kk & 0x80000000u) ? (kk ^ 0x80000000u) : ~kk;
    float logit = __uint_as_float(ub);
    float score = 1.0f / (1.0f + expf(-logit));

    float4 a  = *(const float4*)(anchors + (size_t)idx * 4);
    float4 dl = *(const float4*)(deltas + ((size_t)img * A + idx) * 4);

    float wa  = __fsub_rn(a.z, a.x);
    float ha  = __fsub_rn(a.w, a.y);
    float cxa = __fadd_rn(a.x, __fmul_rn(0.5f, wa));
    float cya = __fadd_rn(a.y, __fmul_rn(0.5f, ha));
    float dw  = fminf(dl.z, BBOXCLIP);
    float dh  = fminf(dl.w, BBOXCLIP);
    float pcx = __fadd_rn(__fmul_rn(dl.x, wa), cxa);
    float pcy = __fadd_rn(__fmul_rn(dl.y, ha), cya);
    float pw  = __fmul_rn(expf(dw), wa);
    float ph  = __fmul_rn(expf(dh), ha);
    float x1 = __fsub_rn(pcx, __fmul_rn(0.5f, pw));
    float y1 = __fsub_rn(pcy, __fmul_rn(0.5f, ph));
    float x2 = __fadd_rn(pcx, __fmul_rn(0.5f, pw));
    float y2 = __fadd_rn(pcy, __fmul_rn(0.5f, ph));
    x1 = fminf(fmaxf(x1, 0.0f), IMGSZ);
    y1 = fminf(fmaxf(y1, 0.0f), IMGSZ);
    x2 = fminf(fmaxf(x2, 0.0f), IMGSZ);
    y2 = fminf(fmaxf(y2, 0.0f), IMGSZ);
    float w = __fsub_rn(x2, x1);
    float h = __fsub_rn(y2, y1);

    d_bx1[img][s] = x1; d_by1[img][s] = y1;
    d_bx2[img][s] = x2; d_by2[img][s] = y2;
    d_area[img][s]  = __fmul_rn(w, h);
    d_scoreA[img][s] = score;
    d_validb[img][s] = (w >= MINSZ) && (h >= MINSZ) && (score > 0.0f);
}

// suppression bitmask: d_mask[img][i][cb] bit k set iff j=cb*64+k > i and IoU>thr
__global__ void k_mask() {
    int cb = blockIdx.x, rb = blockIdx.y, img = blockIdx.z;
    if (cb < rb) return;
    __shared__ float cx1[64], cy1[64], cx2[64], cy2[64], ca[64];
    int t = threadIdx.x;
    int j0 = cb * 64;
    int jl = j0 + t; if (jl >= PRE) jl = PRE - 1;
    cx1[t] = d_bx1[img][jl]; cy1[t] = d_by1[img][jl];
    cx2[t] = d_bx2[img][jl]; cy2[t] = d_by2[img][jl];
    ca[t]  = d_area[img][jl];
    __syncthreads();
    int i = rb * 64 + t;
    if (i >= PRE) return;
    float ix1 = d_bx1[img][i], iy1 = d_by1[img][i];
    float ix2 = d_bx2[img][i], iy2 = d_by2[img][i];
    float ia  = d_area[img][i];
    unsigned long long bits = 0ull;
    #pragma unroll 8
    for (int k = 0; k < 64; k++) {
        int j = j0 + k;
        if (j < PRE && j > i) {
            float xx1 = fmaxf(ix1, cx1[k]);
            float yy1 = fmaxf(iy1, cy1[k]);
            float xx2 = fminf(ix2, cx2[k]);
            float yy2 = fminf(iy2, cy2[k]);
            float iw = fmaxf(__fsub_rn(xx2, xx1), 0.0f);
            float ih = fmaxf(__fsub_rn(yy2, yy1), 0.0f);
            float inter = __fmul_rn(iw, ih);
            float den = __fadd_rn(__fsub_rn(__fadd_rn(ia, ca[k]), inter), 1e-12f);
            float iou = __fdiv_rn(inter, den);
            if (iou > IOUTHR) bits |= (1ull << k);
        }
    }
    d_mask[img][i][cb] = bits;
}

// sequential greedy resolve: 1 warp per image
__global__ void k_nms() {
    int img = blockIdx.x;
    int lane = threadIdx.x;
    unsigned long long validw = 0ull;
    for (int k = 0; k < 64; k++) {
        int i = lane * 64 + k;
        if (i < PRE && d_validb[img][i]) validw |= (1ull << k);
    }
    unsigned long long remv = 0ull, keepw = 0ull;
    unsigned long long row = d_mask[img][0][lane];
    for (int i = 0; i < PRE; i++) {
        unsigned long long nrow = (i + 1 < PRE) ? d_mask[img][i + 1][lane] : 0ull;
        int w = i >> 6, b = i & 63;
        int flag = 0;
        if (lane == w)
            flag = (int)((validw >> b) & 1ull) & (int)(1ull ^ ((remv >> b) & 1ull));
        flag = __shfl_sync(0xffffffffu, flag, w);
        if (flag) {
            remv |= row;
            if (lane == w) keepw |= (1ull << b);
        }
        row = nrow;
    }
    d_keep[img][lane] = keepw;
}

// stable partition (kept in score order, then suppressed in positional order)
__global__ void k_out(float* __restrict__ out) {
    __shared__ int pref[33];
    __shared__ unsigned long long kw[32];
    int img = blockIdx.x;
    if (threadIdx.x < 32) kw[threadIdx.x] = d_keep[img][threadIdx.x];
    __syncthreads();
    if (threadIdx.x == 0) {
        int acc = 0;
        for (int w = 0; w < 32; w++) { pref[w] = acc; acc += __popcll(kw[w]); }
        pref[32] = acc;
    }
    __syncthreads();
    int cnt = pref[32];
    for (int p = threadIdx.x; p < PRE; p += blockDim.x) {
        int w = p >> 6, b = p & 63;
        unsigned long long word = kw[w];
        int before = pref[w] + __popcll(word & ((b == 0) ? 0ull : ((~0ull) >> (64 - b))));
        bool kp = (word >> b) & 1ull;
        int slot = kp ? before : (cnt + (p - before));
        if (slot < POST) {
            float* o = out + ((size_t)img * POST + slot) * 5;
            o[0] = d_bx1[img][p]; o[1] = d_by1[img][p];
            o[2] = d_bx2[img][p]; o[3] = d_by2[img][p];
            o[4] = kp ? d_scoreA[img][p] : 0.0f;
        }
    }
}

// ------------------------------- launch ------------------------------------
extern "C" void kernel_launch(void* const* d_in, const int* in_sizes, int n_in,
                              void* d_out, int out_size) {
    const float* obj     = (const float*)d_in[0];
    const float* deltas  = (const float*)d_in[1];
    const float* anchors = (const float*)d_in[2];
    float* out = (float*)d_out;

    int A = in_sizes[2] / 4;
    int N = in_sizes[0] / A;
    if (N > NMAXI) N = NMAXI;

    dim3 scanGrid(96, N);
    k_init<<<N, 256>>>();
    for (int p = 0; p < 4; p++) {
        k_hist<<<scanGrid, 256>>>(obj, A, p);
        k_pick<<<1, N>>>(p);
    }
    k_compact<<<scanGrid, 256>>>(obj, A);
    k_sortfill<<<N, 1024>>>();
    k_decode<<<(N * PRE + 255) / 256, 256>>>(deltas, anchors, A, N);
    k_mask<<<dim3(32, 32, N), 64>>>();
    k_nms<<<N, 32>>>();
    k_out<<<N, 256>>>(out);
}

// round 2
// speedup vs baseline: 1.7463x; 1.7463x over previous
#include <cuda_runtime.h>
#include <cstdint>

#define NMAXI 8
#define PRE   2000
#define POST  1000
#define CAP   2048
#define WORDS 32
#define TIECAP 1024
#define BANDCAP 65536

#define IMGSZ 800.0f
#define IOUTHR 0.7f
#define MINSZ 1e-3f
#define BBOXCLIP 4.135166556742356f   // log(1000/16)

// ------------------------- device scratch (static) -------------------------
__device__ unsigned int       d_hist[NMAXI][256];
__device__ unsigned int       d_prefix[NMAXI];
__device__ int                d_rankr[NMAXI];
__device__ int                d_cntG[NMAXI], d_cntE[NMAXI], d_bandCnt[NMAXI];
__device__ int                d_tie[NMAXI][TIECAP];
__device__ unsigned long long d_band[NMAXI][BANDCAP];
__device__ unsigned long long d_cand[NMAXI][CAP];
__device__ unsigned long long d_asort[NMAXI][CAP];
__device__ float              d_bx1[NMAXI][CAP], d_by1[NMAXI][CAP];
__device__ float              d_bx2[NMAXI][CAP], d_by2[NMAXI][CAP];
__device__ float              d_area[NMAXI][CAP], d_scoreA[NMAXI][CAP];
__device__ unsigned char      d_validb[NMAXI][CAP];
__device__ unsigned long long d_mask[NMAXI][CAP][WORDS];
__device__ unsigned long long d_rowAny[NMAXI][WORDS];
__device__ unsigned long long d_keep[NMAXI][WORDS];

__device__ __forceinline__ unsigned key_of(float f) {
    unsigned u = __float_as_uint(f);
    return (u & 0x80000000u) ? ~u : (u | 0x80000000u);
}

// ------------------------------- kernels -----------------------------------
__global__ void k_init() {
    int img = blockIdx.x;
    d_hist[img][threadIdx.x] = 0u;
    if (threadIdx.x < WORDS) d_rowAny[img][threadIdx.x] = 0ull;
    if (threadIdx.x == 0) {
        d_prefix[img] = 0u; d_rankr[img] = PRE;
        d_cntG[img] = 0; d_cntE[img] = 0; d_bandCnt[img] = 0;
    }
}

__global__ void k_zero() {
    size_t total = (size_t)NMAXI * CAP * WORDS;
    unsigned long long* p = &d_mask[0][0][0];
    size_t stride = (size_t)gridDim.x * blockDim.x;
    for (size_t i = blockIdx.x * (size_t)blockDim.x + threadIdx.x; i < total; i += stride)
        p[i] = 0ull;
}

// pass-0 histogram over full data (float4 vectorized)
__global__ void k_hist0(const float4* __restrict__ obj4, int A4) {
    __shared__ unsigned sh[256];
    int img = blockIdx.y;
    sh[threadIdx.x] = 0u;
    __syncthreads();
    const float4* base = obj4 + (size_t)img * A4;
    int stride = gridDim.x * blockDim.x;
    for (int i = blockIdx.x * blockDim.x + threadIdx.x; i < A4; i += stride) {
        float4 v = base[i];
        atomicAdd(&sh[key_of(v.x) >> 24], 1u);
        atomicAdd(&sh[key_of(v.y) >> 24], 1u);
        atomicAdd(&sh[key_of(v.z) >> 24], 1u);
        atomicAdd(&sh[key_of(v.w) >> 24], 1u);
    }
    __syncthreads();
    if (sh[threadIdx.x]) atomicAdd(&d_hist[img][threadIdx.x], sh[threadIdx.x]);
}

// parallel bin pick via shared suffix-scan; also zeroes histogram
__global__ void k_pick(int pass) {
    __shared__ unsigned s[256];
    int img = blockIdx.x, v = threadIdx.x;
    unsigned R = (unsigned)d_rankr[img];
    s[v] = d_hist[img][v];
    __syncthreads();
    for (int off = 1; off < 256; off <<= 1) {
        unsigned add = (v + off < 256) ? s[v + off] : 0u;
        __syncthreads();
        s[v] += add;
        __syncthreads();
    }
    unsigned Sv = s[v];
    unsigned Sn = (v < 255) ? s[v + 1] : 0u;
    if (Sv >= R && (v == 255 || Sn < R)) {
        d_rankr[img]  = (int)(R - Sn);
        d_prefix[img] |= ((unsigned)v) << (24 - 8 * pass);
    }
    d_hist[img][v] = 0u;
}

// compact candidate band (top byte >= b0) from full data
__global__ void k_band(const float4* __restrict__ obj4, int A4) {
    int img = blockIdx.y;
    unsigned thr = (d_prefix[img] >> 24) << 24;
    const float4* base = obj4 + (size_t)img * A4;
    int stride = gridDim.x * blockDim.x;
    for (int i = blockIdx.x * blockDim.x + threadIdx.x; i < A4; i += stride) {
        float4 v = base[i];
        unsigned k0 = key_of(v.x), k1 = key_of(v.y), k2 = key_of(v.z), k3 = key_of(v.w);
        int c = (k0 >= thr) + (k1 >= thr) + (k2 >= thr) + (k3 >= thr);
        if (c) {
            int pos = atomicAdd(&d_bandCnt[img], c);
            unsigned bi = (unsigned)i * 4u;
            if (k0 >= thr) { if (pos < BANDCAP) d_band[img][pos] = ((unsigned long long)k0 << 32) | (unsigned)~(bi + 0); pos++; }
            if (k1 >= thr) { if (pos < BANDCAP) d_band[img][pos] = ((unsigned long long)k1 << 32) | (unsigned)~(bi + 1); pos++; }
            if (k2 >= thr) { if (pos < BANDCAP) d_band[img][pos] = ((unsigned long long)k2 << 32) | (unsigned)~(bi + 2); pos++; }
            if (k3 >= thr) { if (pos < BANDCAP) d_band[img][pos] = ((unsigned long long)k3 << 32) | (unsigned)~(bi + 3); pos++; }
        }
    }
}

// radix histogram over band for passes 1..3
__global__ void k_hist2(int pass) {
    __shared__ unsigned sh[256];
    int img = blockIdx.y;
    sh[threadIdx.x] = 0u;
    __syncthreads();
    unsigned pref = d_prefix[img];
    int shift = 24 - 8 * pass;
    int n = d_bandCnt[img]; if (n > BANDCAP) n = BANDCAP;
    int stride = gridDim.x * blockDim.x;
    for (int i = blockIdx.x * blockDim.x + threadIdx.x; i < n; i += stride) {
        unsigned u = (unsigned)(d_band[img][i] >> 32);
        if (((u ^ pref) >> (shift + 8)) == 0u) atomicAdd(&sh[(u >> shift) & 255u], 1u);
    }
    __syncthreads();
    if (sh[threadIdx.x]) atomicAdd(&d_hist[img][threadIdx.x], sh[threadIdx.x]);
}

__global__ void k_compact2() {
    int img = blockIdx.y;
    unsigned T = d_prefix[img];
    int n = d_bandCnt[img]; if (n > BANDCAP) n = BANDCAP;
    int stride = gridDim.x * blockDim.x;
    for (int i = blockIdx.x * blockDim.x + threadIdx.x; i < n; i += stride) {
        unsigned long long pk = d_band[img][i];
        unsigned u = (unsigned)(pk >> 32);
        if (u > T) {
            int pos = atomicAdd(&d_cntG[img], 1);
            if (pos < CAP) d_cand[img][pos] = pk;
        } else if (u == T) {
            int pos = atomicAdd(&d_cntE[img], 1);
            if (pos < TIECAP) d_tie[img][pos] = (int)~(unsigned)pk;
        }
    }
}

// fill ties, pad, bitonic sort 2048 descending (key desc, ties: index asc)
__global__ void k_sortfill() {
    __shared__ unsigned long long sh[CAP];
    int img = blockIdx.x;
    int cg = d_cntG[img]; if (cg > PRE) cg = PRE;
    for (int idx = threadIdx.x; idx < CAP; idx += blockDim.x)
        sh[idx] = (idx < cg) ? d_cand[img][idx] : 0ull;
    __syncthreads();
    if (threadIdx.x == 0) {
        int ce = d_cntE[img]; if (ce > TIECAP) ce = TIECAP;
        int need = PRE - cg; if (need < 0) need = 0; if (need > ce) need = ce;
        unsigned long long T64 = (unsigned long long)d_prefix[img] << 32;
        for (int r = 0; r < need; r++) {
            int best = -1, bi = 0;
            for (int t = 0; t < ce; t++) {
                int v = d_tie[img][t];
                if (v >= 0 && (best < 0 || v < best)) { best = v; bi = t; }
            }
            d_tie[img][bi] = -1;
            sh[cg + r] = T64 | (unsigned)~(unsigned)best;
        }
    }
    __syncthreads();
    for (unsigned k = 2; k <= CAP; k <<= 1) {
        for (unsigned j = k >> 1; j > 0; j >>= 1) {
            for (unsigned idx = threadIdx.x; idx < CAP; idx += blockDim.x) {
                unsigned ixj = idx ^ j;
                if (ixj > idx) {
                    bool up = ((idx & k) == 0);
                    unsigned long long a = sh[idx], b = sh[ixj];
                    bool sw = up ? (a < b) : (a > b);
                    if (sw) { sh[idx] = b; sh[ixj] = a; }
                }
            }
            __syncthreads();
        }
    }
    for (int idx = threadIdx.x; idx < CAP; idx += blockDim.x)
        d_cand[img][idx] = sh[idx];
}

__global__ void k_decode(const float* __restrict__ deltas,
                         const float* __restrict__ anchors, int A, int N) {
    int t = blockIdx.x * blockDim.x + threadIdx.x;
    if (t >= N * CAP) return;
    int img = t / CAP, s = t % CAP;
    if (s >= PRE) {   // padding: sorts last by area, never enters any window
        d_area[img][s]  = -1.0f;
        d_asort[img][s] = ((unsigned long long)key_of(-1.0f) << 32) | (unsigned)s;
        return;
    }
    unsigned long long pk = d_cand[img][s];
    unsigned idx = ~(unsigned)(pk & 0xffffffffu);
    unsigned kk  = (unsigned)(pk >> 32);
    unsigned ub  = (kk & 0x80000000u) ? (kk ^ 0x80000000u) : ~kk;
    float logit = __uint_as_float(ub);
    float score = 1.0f / (1.0f + expf(-logit));

    float4 a  = *(const float4*)(anchors + (size_t)idx * 4);
    float4 dl = *(const float4*)(deltas + ((size_t)img * A + idx) * 4);

    float wa  = __fsub_rn(a.z, a.x);
    float ha  = __fsub_rn(a.w, a.y);
    float cxa = __fadd_rn(a.x, __fmul_rn(0.5f, wa));
    float cya = __fadd_rn(a.y, __fmul_rn(0.5f, ha));
    float dw  = fminf(dl.z, BBOXCLIP);
    float dh  = fminf(dl.w, BBOXCLIP);
    float pcx = __fadd_rn(__fmul_rn(dl.x, wa), cxa);
    float pcy = __fadd_rn(__fmul_rn(dl.y, ha), cya);
    float pw  = __fmul_rn(expf(dw), wa);
    float ph  = __fmul_rn(expf(dh), ha);
    float x1 = __fsub_rn(pcx, __fmul_rn(0.5f, pw));
    float y1 = __fsub_rn(pcy, __fmul_rn(0.5f, ph));
    float x2 = __fadd_rn(pcx, __fmul_rn(0.5f, pw));
    float y2 = __fadd_rn(pcy, __fmul_rn(0.5f, ph));
    x1 = fminf(fmaxf(x1, 0.0f), IMGSZ);
    y1 = fminf(fmaxf(y1, 0.0f), IMGSZ);
    x2 = fminf(fmaxf(x2, 0.0f), IMGSZ);
    y2 = fminf(fmaxf(y2, 0.0f), IMGSZ);
    float w = __fsub_rn(x2, x1);
    float h = __fsub_rn(y2, y1);
    float ar = __fmul_rn(w, h);

    d_bx1[img][s] = x1; d_by1[img][s] = y1;
    d_bx2[img][s] = x2; d_by2[img][s] = y2;
    d_area[img][s]   = ar;
    d_scoreA[img][s] = score;
    d_validb[img][s] = (w >= MINSZ) && (h >= MINSZ) && (score > 0.0f);
    d_asort[img][s]  = ((unsigned long long)key_of(ar) << 32) | (unsigned)s;
}

// bitonic sort by area descending
__global__ void k_areasort() {
    __shared__ unsigned long long sh[CAP];
    int img = blockIdx.x;
    for (int i = threadIdx.x; i < CAP; i += blockDim.x) sh[i] = d_asort[img][i];
    __syncthreads();
    for (unsigned k = 2; k <= CAP; k <<= 1) {
        for (unsigned j = k >> 1; j > 0; j >>= 1) {
            for (unsigned idx = threadIdx.x; idx < CAP; idx += blockDim.x) {
                unsigned ixj = idx ^ j;
                if (ixj > idx) {
                    bool up = ((idx & k) == 0);
                    unsigned long long a = sh[idx], b = sh[ixj];
                    bool sw = up ? (a < b) : (a > b);
                    if (sw) { sh[idx] = b; sh[ixj] = a; }
                }
            }
            __syncthreads();
        }
    }
    for (int i = threadIdx.x; i < CAP; i += blockDim.x) d_asort[img][i] = sh[i];
}

// exact IoU only inside the area-compatible window (IoU <= min/max area)
__global__ void k_pairs() {
    int img  = blockIdx.y;
    int p    = blockIdx.x * (blockDim.x >> 5) + (threadIdx.x >> 5);
    int lane = threadIdx.x & 31;
    if (p >= CAP - 1) return;
    unsigned long long ep = d_asort[img][p];
    int sp = (int)(unsigned)(ep & 0xffffffffull);
    float ap = d_area[img][sp];
    if (ap < 0.0f) return;                     // padding
    float thr = 0.69f * ap;                    // safe superset of ratio >= 0.7
    float ix1 = d_bx1[img][sp], iy1 = d_by1[img][sp];
    float ix2 = d_bx2[img][sp], iy2 = d_by2[img][sp];
    for (int qb = p + 1; qb < CAP; qb += 32) {
        int q = qb + lane;
        bool act = false; int sq = 0; float aq = 0.0f;
        if (q < CAP) {
            sq = (int)(unsigned)(d_asort[img][q] & 0xffffffffull);
            aq = d_area[img][sq];
            act = (aq >= thr);
        }
        if (act) {
            float xx1 = fmaxf(ix1, d_bx1[img][sq]);
            float yy1 = fmaxf(iy1, d_by1[img][sq]);
            float xx2 = fminf(ix2, d_bx2[img][sq]);
            float yy2 = fminf(iy2, d_by2[img][sq]);
            float iw = fmaxf(__fsub_rn(xx2, xx1), 0.0f);
            float ih = fmaxf(__fsub_rn(yy2, yy1), 0.0f);
            float inter = __fmul_rn(iw, ih);
            float den = __fadd_rn(__fsub_rn(__fadd_rn(ap, aq), inter), 1e-12f);
            float iou = __fdiv_rn(inter, den);
            if (iou > IOUTHR) {
                int i = sp < sq ? sp : sq;
                int j = sp < sq ? sq : sp;
                atomicOr(&d_mask[img][i][j >> 6], 1ull << (j & 63));
                atomicOr(&d_rowAny[img][i >> 6], 1ull << (i & 63));
            }
        }
        if (__ballot_sync(0xffffffffu, act) != 0xffffffffu) break;
    }
}

// sparse greedy resolve: 1 warp per image, chunked 64 rows at a time
__global__ void k_nms() {
    int img = blockIdx.x, lane = threadIdx.x;
    unsigned long long validw = 0ull;
    for (int k = 0; k < 64; k++) {
        int i = lane * 64 + k;
        if (i < PRE && d_validb[img][i]) validw |= 1ull << k;
    }
    unsigned long long remv = 0ull, keepw = 0ull;
    unsigned long long rowAny_l = d_rowAny[img][lane];
    unsigned long long dg0 = d_mask[img][lane][0];
    unsigned long long dg1 = d_mask[img][32 + lane][0];
    for (int c = 0; c < 32; c++) {
        unsigned long long ndg0 = 0ull, ndg1 = 0ull;
        if (c < 31) {   // prefetch next chunk's diagonal words
            ndg0 = d_mask[img][(c + 1) * 64 + lane][c + 1];
            ndg1 = d_mask[img][(c + 1) * 64 + 32 + lane][c + 1];
        }
        unsigned long long vw = __shfl_sync(0xffffffffu, validw, c);
        unsigned long long rm = __shfl_sync(0xffffffffu, remv, c);
        unsigned b0 = __ballot_sync(0xffffffffu, dg0 != 0ull);
        unsigned b1 = __ballot_sync(0xffffffffu, dg1 != 0ull);
        unsigned long long D = (unsigned long long)b0 | ((unsigned long long)b1 << 32);
        unsigned long long keep = 0ull;
        int pos = 0;
        unsigned long long Dw = D;
        while (Dw) {    // identical across lanes
            int r = __ffsll((long long)Dw) - 1; Dw &= Dw - 1;
            unsigned long long rangeM = ((1ull << (r - pos)) - 1ull) << pos;
            keep |= vw & ~rm & rangeM;
            unsigned long long dr = (r < 32) ? __shfl_sync(0xffffffffu, dg0, r)
                                             : __shfl_sync(0xffffffffu, dg1, r - 32);
            if (((vw >> r) & 1ull) && !((rm >> r) & 1ull)) { keep |= 1ull << r; rm |= dr; }
            pos = r + 1;
        }
        if (pos < 64) keep |= vw & ~rm & ((~0ull) << pos);
        if (lane == c) keepw = keep;
        unsigned long long rAc = __shfl_sync(0xffffffffu, rowAny_l, c);
        unsigned long long todo = keep & rAc;   // identical across lanes
        while (todo) {
            int r = __ffsll((long long)todo) - 1; todo &= todo - 1;
            remv |= d_mask[img][c * 64 + r][lane];
        }
        dg0 = ndg0; dg1 = ndg1;
    }
    d_keep[img][lane] = keepw;
}

// stable partition: kept (score order) first, then suppressed (positional)
__global__ void k_out(float* __restrict__ out) {
    __shared__ int pref[33];
    __shared__ unsigned long long kw[32];
    int img = blockIdx.x;
    if (threadIdx.x < 32) kw[threadIdx.x] = d_keep[img][threadIdx.x];
    __syncthreads();
    if (threadIdx.x == 0) {
        int acc = 0;
        for (int w = 0; w < 32; w++) { pref[w] = acc; acc += __popcll(kw[w]); }
        pref[32] = acc;
    }
    __syncthreads();
    int cnt = pref[32];
    for (int p = threadIdx.x; p < PRE; p += blockDim.x) {
        int w = p >> 6, b = p & 63;
        unsigned long long word = kw[w];
        int before = pref[w] + __popcll(word & ((b == 0) ? 0ull : ((~0ull) >> (64 - b))));
        bool kp = (word >> b) & 1ull;
        int slot = kp ? before : (cnt + (p - before));
        if (slot < POST) {
            float* o = out + ((size_t)img * POST + slot) * 5;
            o[0] = d_bx1[img][p]; o[1] = d_by1[img][p];
            o[2] = d_bx2[img][p]; o[3] = d_by2[img][p];
            o[4] = kp ? d_scoreA[img][p] : 0.0f;
        }
    }
}

// ------------------------------- launch ------------------------------------
extern "C" void kernel_launch(void* const* d_in, const int* in_sizes, int n_in,
                              void* d_out, int out_size) {
    const float* obj     = (const float*)d_in[0];
    const float* deltas  = (const float*)d_in[1];
    const float* anchors = (const float*)d_in[2];
    float* out = (float*)d_out;

    int A = in_sizes[2] / 4;
    int N = in_sizes[0] / A;
    if (N > NMAXI) N = NMAXI;
    int A4 = A / 4;

    k_init<<<N, 256>>>();
    k_zero<<<512, 256>>>();
    k_hist0<<<dim3(96, N), 256>>>((const float4*)obj, A4);
    k_pick<<<N, 256>>>(0);
    k_band<<<dim3(96, N), 256>>>((const float4*)obj, A4);
    for (int p = 1; p < 4; p++) {
        k_hist2<<<dim3(8, N), 256>>>(p);
        k_pick<<<N, 256>>>(p);
    }
    k_compact2<<<dim3(8, N), 256>>>();
    k_sortfill<<<N, 1024>>>();
    k_decode<<<(N * CAP + 255) / 256, 256>>>(deltas, anchors, A, N);
    k_areasort<<<N, 1024>>>();
    k_pairs<<<dim3(CAP / 8, N), 256>>>();
    k_nms<<<N, 32>>>();
    k_out<<<N, 256>>>(out);
}